// round 11
// baseline (speedup 1.0000x reference)
#include <cuda_runtime.h>
#include <cuda_fp16.h>
#include <mma.h>

using namespace nvcuda;

// Problem constants
#define B_    8
#define C_    64
#define CP_   80    // padded c: 64 real + 1 bias channel + 15 zero (5 k-tiles of 16)
#define N_    4096
#define K_    16
#define OUT_  64
#define R_    128   // 2*OUT rows: [0,64) = u (=(W1-W2)x + bias), [64,128) = v (=W2 x)

#define NT_   64             // nodes per block tile (gemm)
#define LDA   72             // sA: half[CP_][LDA]
#define LDB   136            // sB: half[CP_][LDB]
#define LDS_  136            // scratch: float[NT_][LDS_]
#define SA_BYTES (CP_ * LDA * 2)            // 11,520
#define SB_BYTES (CP_ * LDB * 2)            // 21,760
#define SMEM_BYTES (NT_ * LDS_ * 4)         // 34,816 (scratch unions over sA+sB)

// Scratch (device global — no allocation allowed)
__device__ __half g_uvh[B_ * N_ * R_];   // [b][n][r] half: row = 256B = [u 0..63 | v 0..63]

// ---- PDL griddepcontrol (sm_90+) -------------------------------------------
__device__ __forceinline__ void gdc_wait() {
    asm volatile("griddepcontrol.wait;" ::: "memory");
}
__device__ __forceinline__ void gdc_launch_dependents() {
    asm volatile("griddepcontrol.launch_dependents;" ::: "memory");
}

// ---------------------------------------------------------------------------
// Kernel 1 (HMMA, per batch b): uv[n][r] = sum_c x[c][n]*Wt[c][r], bias as c=64.
// No dependency on predecessor (writes only uvh[b]) -> trigger at entry so the
// paired gather_b launches early; no gdc_wait needed (disjoint buffers, and the
// post-wait trigger in gather guarantees all older readers of uvh[b] finished).
// ---------------------------------------------------------------------------
__global__ void __launch_bounds__(128) gemm_uv(const float* __restrict__ x,
                                               const float* __restrict__ W,
                                               const float* __restrict__ bias,
                                               int b) {
    gdc_launch_dependents();   // successor (gather_b) self-gates via gdc_wait

    extern __shared__ char dyn[];
    __half* sA = (__half*)dyn;                 // [CP_][LDA]
    __half* sB = (__half*)(dyn + SA_BYTES);    // [CP_][LDB]
    float*  sc = (float*)dyn;                  // [NT_][LDS_] (union, after sync)

    const int n0 = blockIdx.x * NT_;
    const int t  = threadIdx.x;
    const int wn = t >> 5;        // warp id = n-subtile (16 nodes each)

    // ---- sA[c][nl]: x tile (c<64), bias channel (c=64 -> 1.0), zero pad
    for (int lin = t; lin < CP_ * NT_; lin += 128) {
        int c  = lin >> 6;
        int nl = lin & (NT_ - 1);
        float v;
        if (c < 64)       v = x[((b * C_ + c) * N_) + n0 + nl];
        else if (c == 64) v = 1.0f;
        else              v = 0.0f;
        sA[c * LDA + nl] = __float2half(v);
    }
    // ---- sB[c][r]: fused weight transform (c<64)
    for (int lin = t; lin < C_ * OUT_; lin += 128) {
        int c = lin & 63;
        int r = lin >> 6;                 // 0..63
        float a  = W[r * 128 + c];        // W1[r][c]
        float bb = W[r * 128 + 64 + c];   // W2[r][c]
        sB[c * LDB + r]      = __float2half(a - bb);
        sB[c * LDB + r + 64] = __float2half(bb);
    }
    // ---- sB rows 64..79: bias row + zeros
    for (int lin = t; lin < 16 * R_; lin += 128) {
        int c = 64 + (lin >> 7);
        int r = lin & 127;
        float v = (c == 64 && r < 64) ? bias[r] : 0.0f;
        sB[c * LDB + r] = __float2half(v);
    }
    __syncthreads();

    // ---- MMA: warp wn computes rows [wn*16, wn*16+16) x 128 r, 5 k-tiles
    wmma::fragment<wmma::matrix_a, 16, 16, 16, __half, wmma::col_major> fa[5];
    #pragma unroll
    for (int k = 0; k < 5; k++)
        wmma::load_matrix_sync(fa[k], sA + (k * 16) * LDA + wn * 16, LDA);

    wmma::fragment<wmma::accumulator, 16, 16, 16, float> fc[8];
    #pragma unroll
    for (int rt = 0; rt < 8; rt++) {
        wmma::fill_fragment(fc[rt], 0.0f);
        #pragma unroll
        for (int k = 0; k < 5; k++) {
            wmma::fragment<wmma::matrix_b, 16, 16, 16, __half, wmma::row_major> fb;
            wmma::load_matrix_sync(fb, sB + (k * 16) * LDB + rt * 16, LDB);
            wmma::mma_sync(fc[rt], fa[k], fb, fc[rt]);
        }
    }
    __syncthreads();   // all warps done with sA/sB before scratch overwrite

    #pragma unroll
    for (int rt = 0; rt < 8; rt++)
        wmma::store_matrix_sync(sc + (wn * 16) * LDS_ + rt * 16, fc[rt],
                                LDS_, wmma::mem_row_major);
    __syncthreads();

    // ---- epilogue: fp16 convert + node-major store (bias already folded in)
    __half* outb = g_uvh + (size_t)(b * N_ + n0) * R_;
    for (int idx = t; idx < NT_ * 64; idx += 128) {   // half2 granularity
        int nl = idx >> 6;
        int rp = idx & 63;
        float lo = sc[nl * LDS_ + 2 * rp];
        float hi = sc[nl * LDS_ + 2 * rp + 1];
        *(__half2*)(outb + nl * R_ + 2 * rp) = __floats2half2_rn(lo, hi);
    }
}

// ---------------------------------------------------------------------------
// Kernel 2 (per batch b): out[b][o][n] = max_k relu(u[i1][o] + v[i0][o])
// PDL: stage edge indices (independent) -> gdc_wait (gemm_b done) -> trigger
// (safe point: everything older has completed) -> gather at the L2 roofline.
// ---------------------------------------------------------------------------
__global__ void __launch_bounds__(256) gather_max(const int* __restrict__ edge,
                                                  float* __restrict__ out,
                                                  int b) {
    __shared__ int2  sIdx[32][17];   // [node_local][k] (i0,i1); pad bank-clean
    __shared__ float sm[OUT_][33];   // transpose stage, pad 32->33

    const int n0 = blockIdx.x * 32;
    const int t  = threadIdx.x;

    // Prologue (overlaps gemm_b tail): stage indices, both directions.
    for (int lin = t; lin < 512; lin += 256) {
        int node = lin >> 4;
        int kk   = lin & 15;
        int e0 = edge[((0 * B_ + b) * N_ + n0 + node) * K_ + kk] & (N_ - 1); // neighbor -> v
        int e1 = edge[((1 * B_ + b) * N_ + n0 + node) * K_ + kk] & (N_ - 1); // center   -> u
        sIdx[node][kk] = make_int2(e0, e1);
    }
    __syncthreads();

    gdc_wait();                 // uvh[b] ready (gemm_b complete)
    gdc_launch_dependents();    // now gemm_{b+1} may run concurrently

    const int w    = t >> 5;
    const int lane = t & 31;
    const int h    = lane >> 3;          // node slot 0..3
    const int sl   = lane & 7;           // channel group: halves [8*sl, 8*sl+8)
    const int nl   = 4 * w + h;          // node local 0..31

    const __half* uvb = g_uvh + (size_t)b * N_ * R_;
    const int co = 8 * sl;               // half offset of this lane's channels

    __half2 m0 = __float2half2_rn(0.0f);
    __half2 m1 = m0, m2 = m0, m3 = m0;

    #pragma unroll
    for (int kk = 0; kk < K_; kk++) {
        int2 p = sIdx[nl][kk];           // broadcast within 8-lane group
        uint4 uu = *(const uint4*)(uvb + p.y * R_ + co);        // u[co..co+7]
        uint4 vv = *(const uint4*)(uvb + p.x * R_ + 64 + co);   // v[co..co+7]
        m0 = __hmax2(m0, __hadd2(*(__half2*)&uu.x, *(__half2*)&vv.x));
        m1 = __hmax2(m1, __hadd2(*(__half2*)&uu.y, *(__half2*)&vv.y));
        m2 = __hmax2(m2, __hadd2(*(__half2*)&uu.z, *(__half2*)&vv.z));
        m3 = __hmax2(m3, __hadd2(*(__half2*)&uu.w, *(__half2*)&vv.w));
    }

    // Transpose stage: lane owns channels co..co+7 of node nl.
    float2 f;
    f = __half22float2(m0); sm[co + 0][nl] = f.x; sm[co + 1][nl] = f.y;
    f = __half22float2(m1); sm[co + 2][nl] = f.x; sm[co + 3][nl] = f.y;
    f = __half22float2(m2); sm[co + 4][nl] = f.x; sm[co + 5][nl] = f.y;
    f = __half22float2(m3); sm[co + 6][nl] = f.x; sm[co + 7][nl] = f.y;
    __syncthreads();

    #pragma unroll
    for (int it = 0; it < 8; it++) {
        int lin = t + it * 256;          // 2048 values: 64 o x 32 n
        int o   = lin >> 5;
        int nn  = lin & 31;
        out[((b * OUT_ + o) * N_) + n0 + nn] = sm[o][nn];
    }
}

// ---------------------------------------------------------------------------
extern "C" void kernel_launch(void* const* d_in, const int* in_sizes, int n_in,
                              void* d_out, int out_size) {
    const float* x    = (const float*)d_in[0];
    const int*   edge = (const int*)d_in[1];
    const float* W    = (const float*)d_in[2];
    const float* bias = (const float*)d_in[3];
    float*       out  = (float*)d_out;

    cudaLaunchAttribute attr[1];
    attr[0].id = cudaLaunchAttributeProgrammaticStreamSerialization;
    attr[0].val.programmaticStreamSerializationAllowed = 1;

    cudaLaunchConfig_t cfg = {};
    cfg.attrs = attr;
    cfg.numAttrs = 1;

    for (int b = 0; b < B_; b++) {
        cfg.gridDim = dim3(N_ / NT_, 1, 1);
        cfg.blockDim = dim3(128, 1, 1);
        cfg.dynamicSmemBytes = SMEM_BYTES;          // 34,816 < 48KB default cap
        cudaLaunchKernelEx(&cfg, gemm_uv, x, W, bias, b);

        cfg.gridDim = dim3(N_ / 32, 1, 1);
        cfg.blockDim = dim3(256, 1, 1);
        cfg.dynamicSmemBytes = 0;
        cudaLaunchKernelEx(&cfg, gather_max, edge, out, b);
    }
}

// round 12
// speedup vs baseline: 2.0506x; 2.0506x over previous
#include <cuda_runtime.h>
#include <cuda_fp16.h>
#include <mma.h>

using namespace nvcuda;

// Problem constants
#define B_    8
#define C_    64
#define CP_   80    // padded c: 64 real + 1 bias channel + 15 zero (5 k-tiles)
#define N_    4096
#define K_    16
#define OUT_  64
#define R_    128   // [0,64) = u = (W1-W2)x + bias, [64,128) = v = W2 x

#define NT_   64             // nodes per block tile (both phases)
#define GRID_ 512            // 8 batches x 64 tiles; co-resident (4/SM x 148 = 592)
#define LDA   72             // sA: half[CP_][LDA]
#define LDB   136            // sB: half[CP_][LDB]
#define LDS_  136            // scratch: float[NT_][LDS_]
#define SA_BYTES (CP_ * LDA * 2)            // 11,520
#define SMEM_BYTES (NT_ * LDS_ * 4)         // 34,816 (unions everything)

// Scratch + barrier (device globals — no allocation allowed)
__device__ __half g_uvh[B_ * N_ * R_];   // [b][n][r]: row = 256B = [u 0..63 | v 0..63]
__device__ unsigned g_bar  = 0;
__device__ unsigned g_done = 0;

// ---------------------------------------------------------------------------
// ONE persistent kernel. Phase 1: HMMA gemm tile (uv = [Wd;W2]·x, bias folded
// as channel 64) + gather-index staging. Device-wide barrier (all 512 blocks
// co-resident by __launch_bounds__(256,4): regs<=64, smem 34.8KB -> 4 CTA/SM).
// Phase 2: gather/max tile at the L2 roofline with explicit load pipelining.
// ---------------------------------------------------------------------------
__global__ void __launch_bounds__(256, 4)
fused_graphconv(const float* __restrict__ x,
                const int*   __restrict__ edge,
                const float* __restrict__ W,
                const float* __restrict__ bias,
                float* __restrict__ out) {
    extern __shared__ char dyn[];
    __half* sA = (__half*)dyn;                    // [CP_][LDA]
    __half* sB = (__half*)(dyn + SA_BYTES);       // [CP_][LDB]
    float*  sc = (float*)dyn;                     // [NT_][LDS_] (union, after sync)

    const int t  = threadIdx.x;
    const int b  = blockIdx.x >> 6;               // batch
    const int n0 = (blockIdx.x & 63) * NT_;       // node base of this tile

    // ================= Phase 1: GEMM tile =================
    // sA[c][nl]: x tile (c<64), bias channel (c=64 -> 1.0), zero pad
    for (int lin = t; lin < CP_ * NT_; lin += 256) {
        int c  = lin >> 6;
        int nl = lin & (NT_ - 1);
        float v;
        if (c < 64)       v = x[((b * C_ + c) * N_) + n0 + nl];
        else if (c == 64) v = 1.0f;
        else              v = 0.0f;
        sA[c * LDA + nl] = __float2half(v);
    }
    // sB[c][r]: fused weight transform (c<64)
    for (int lin = t; lin < C_ * OUT_; lin += 256) {
        int c = lin & 63;
        int r = lin >> 6;
        float a  = W[r * 128 + c];        // W1[r][c]
        float bb = W[r * 128 + 64 + c];   // W2[r][c]
        sB[c * LDB + r]      = __float2half(a - bb);
        sB[c * LDB + r + 64] = __float2half(bb);
    }
    // sB rows 64..79: bias row + zeros
    for (int lin = t; lin < 16 * R_; lin += 256) {
        int c = 64 + (lin >> 7);
        int r = lin & 127;
        float v = (c == 64 && r < 64) ? bias[r] : 0.0f;
        sB[c * LDB + r] = __float2half(v);
    }
    __syncthreads();

    // 8 warps: ws = warp&3 -> 16-node row group, wr = warp>>2 -> 64-r half.
    {
        const int wp = t >> 5;
        const int ws = wp & 3;
        const int wr = wp >> 2;

        wmma::fragment<wmma::accumulator, 16, 16, 16, float> fc[4];
        #pragma unroll
        for (int rt = 0; rt < 4; rt++) wmma::fill_fragment(fc[rt], 0.0f);

        #pragma unroll
        for (int k = 0; k < 5; k++) {
            wmma::fragment<wmma::matrix_a, 16, 16, 16, __half, wmma::col_major> fa;
            wmma::load_matrix_sync(fa, sA + (k * 16) * LDA + ws * 16, LDA);
            #pragma unroll
            for (int rt = 0; rt < 4; rt++) {
                wmma::fragment<wmma::matrix_b, 16, 16, 16, __half, wmma::row_major> fb;
                wmma::load_matrix_sync(fb, sB + (k * 16) * LDB + wr * 64 + rt * 16, LDB);
                wmma::mma_sync(fc[rt], fa, fb, fc[rt]);
            }
        }
        __syncthreads();   // all warps done with sA/sB before scratch overwrite

        #pragma unroll
        for (int rt = 0; rt < 4; rt++)
            wmma::store_matrix_sync(sc + (ws * 16) * LDS_ + wr * 64 + rt * 16,
                                    fc[rt], LDS_, wmma::mem_row_major);
        __syncthreads();
    }

    // Epilogue: fp16 convert + node-major store (bias already folded in)
    {
        __half* outb = g_uvh + (size_t)(b * N_ + n0) * R_;
        for (int idx = t; idx < NT_ * 64; idx += 256) {   // half2 granularity
            int nl = idx >> 6;
            int rp = idx & 63;
            float lo = sc[nl * LDS_ + 2 * rp];
            float hi = sc[nl * LDS_ + 2 * rp + 1];
            *(__half2*)(outb + nl * R_ + 2 * rp) = __floats2half2_rn(lo, hi);
        }
    }
    __syncthreads();   // scratch reads done before index staging overwrites dyn

    // ============ Stage gather indices (overlaps other blocks' gemm) ========
    int2  (*sIdx)[17] = (int2 (*)[17])dyn;                 // [64][17]  8,704 B
    float (*sm)[65]   = (float (*)[65])(dyn + 64 * 17 * sizeof(int2)); // 16,640 B

    for (int lin = t; lin < NT_ * K_; lin += 256) {
        int node = lin >> 4;
        int kk   = lin & 15;
        int e0 = edge[((0 * B_ + b) * N_ + n0 + node) * K_ + kk] & (N_ - 1); // neighbor -> v
        int e1 = edge[((1 * B_ + b) * N_ + n0 + node) * K_ + kk] & (N_ - 1); // center   -> u
        sIdx[node][kk] = make_int2(e0, e1);
    }
    __syncthreads();

    // ================= Device-wide barrier =================
    if (t == 0) {
        __threadfence();                       // publish uvh tile
        atomicAdd(&g_bar, 1u);
        while (*((volatile unsigned*)&g_bar) < GRID_) { __nanosleep(64); }
    }
    __syncthreads();

    // ================= Phase 2: gather/max tile =================
    {
        const int nl = t >> 2;            // node local 0..63 (4 threads/node)
        const int q  = t & 3;             // channel quarter
        const int co = 16 * q;            // half offset: channels [co, co+16)

        const __half* uvb = g_uvh + (size_t)b * N_ * R_;

        __half2 m[8];
        #pragma unroll
        for (int j = 0; j < 8; j++) m[j] = __float2half2_rn(0.0f);

        // Software pipeline: next-kk loads issued before current consumption.
        int2 p = sIdx[nl][0];
        uint4 ua = *(const uint4*)(uvb + p.y * R_ + co);
        uint4 ub = *(const uint4*)(uvb + p.y * R_ + co + 8);
        uint4 va = *(const uint4*)(uvb + p.x * R_ + 64 + co);
        uint4 vb = *(const uint4*)(uvb + p.x * R_ + 64 + co + 8);

        #pragma unroll
        for (int kk = 0; kk < K_; kk++) {
            uint4 nua, nub, nva, nvb;
            if (kk < K_ - 1) {
                int2 np = sIdx[nl][kk + 1];
                nua = *(const uint4*)(uvb + np.y * R_ + co);
                nub = *(const uint4*)(uvb + np.y * R_ + co + 8);
                nva = *(const uint4*)(uvb + np.x * R_ + 64 + co);
                nvb = *(const uint4*)(uvb + np.x * R_ + 64 + co + 8);
            }
            m[0] = __hmax2(m[0], __hadd2(*(__half2*)&ua.x, *(__half2*)&va.x));
            m[1] = __hmax2(m[1], __hadd2(*(__half2*)&ua.y, *(__half2*)&va.y));
            m[2] = __hmax2(m[2], __hadd2(*(__half2*)&ua.z, *(__half2*)&va.z));
            m[3] = __hmax2(m[3], __hadd2(*(__half2*)&ua.w, *(__half2*)&va.w));
            m[4] = __hmax2(m[4], __hadd2(*(__half2*)&ub.x, *(__half2*)&vb.x));
            m[5] = __hmax2(m[5], __hadd2(*(__half2*)&ub.y, *(__half2*)&vb.y));
            m[6] = __hmax2(m[6], __hadd2(*(__half2*)&ub.z, *(__half2*)&vb.z));
            m[7] = __hmax2(m[7], __hadd2(*(__half2*)&ub.w, *(__half2*)&vb.w));
            ua = nua; ub = nub; va = nva; vb = nvb;
        }

        // Transpose stage: thread owns channels co..co+15 of node nl.
        #pragma unroll
        for (int j = 0; j < 8; j++) {
            float2 f = __half22float2(m[j]);
            sm[co + 2 * j][nl]     = f.x;
            sm[co + 2 * j + 1][nl] = f.y;
        }
    }
    __syncthreads();

    // Output: 64 o x 64 n, coalesced 256B segments.
    for (int idx = t; idx < OUT_ * NT_; idx += 256) {
        int o  = idx >> 6;
        int nn = idx & 63;
        out[((b * OUT_ + o) * N_) + n0 + nn] = sm[o][nn];
    }

    // Barrier self-reset for next replay (deterministic, graph-safe).
    __syncthreads();
    if (t == 0) {
        unsigned v = atomicAdd(&g_done, 1u);
        if (v == GRID_ - 1) {
            g_bar = 0;
            __threadfence();
            g_done = 0;
        }
    }
}

// ---------------------------------------------------------------------------
extern "C" void kernel_launch(void* const* d_in, const int* in_sizes, int n_in,
                              void* d_out, int out_size) {
    const float* x    = (const float*)d_in[0];
    const int*   edge = (const int*)d_in[1];
    const float* W    = (const float*)d_in[2];
    const float* bias = (const float*)d_in[3];
    float*       out  = (float*)d_out;

    fused_graphconv<<<GRID_, 256, SMEM_BYTES>>>(x, edge, W, bias, out);
}

// round 13
// speedup vs baseline: 2.3744x; 1.1579x over previous
#include <cuda_runtime.h>
#include <cuda_fp16.h>
#include <mma.h>

using namespace nvcuda;

// Problem constants
#define B_    8
#define C_    64
#define CP_   80    // padded c: 64 real + 1 bias channel + 15 zero (5 k-tiles)
#define N_    4096
#define K_    16
#define OUT_  64
#define R_    128   // [0,64) = u = (W1-W2)x + bias, [64,128) = v = W2 x

#define NT_   64             // nodes per gemm tile
#define GT_   32             // nodes per gather tile
#define NGEMM 512            // 8 batches x 64 tiles
#define NGATH 1024           // 8 batches x 128 tiles
#define GRID_ (NGEMM + NGATH)
#define LDA   72
#define LDB   136
#define LDS_  136
#define SA_BYTES (CP_ * LDA * 2)
#define SMEM_BYTES (NT_ * LDS_ * 4)   // 34,816 (max over both roles)

// Device globals (no allocation allowed)
__device__ __half g_uvh[B_ * N_ * R_];   // [b][n][r]: 256B rows = [u 0..63 | v 0..63]
__device__ unsigned g_cnt[B_];           // gemm tiles completed per batch
__device__ unsigned g_done = 0;          // gather blocks retired (for reset)

// ---------------------------------------------------------------------------
// Single launch, role-split grid.
//   bids [0,512):    gemm role  — one 64n x 128r HMMA tile of uv, then signal.
//   bids [512,1536): gather role — stage indices, wait for its batch's 64 gemm
//                    tiles, then gather/max 32 nodes at the L2 roofline.
// Per-batch counters => no global barrier; gather for batch b starts as soon
// as uv[b] is complete, overlapping the remaining batches' gemm work.
// launch_bounds(256,4): regs<=64, 4 CTA/SM -> wave 1 >= 592 blocks >= all
// gemm blocks resident immediately (deadlock-free spin).
// ---------------------------------------------------------------------------
__global__ void __launch_bounds__(256, 4)
fused_graphconv(const float* __restrict__ x,
                const int*   __restrict__ edge,
                const float* __restrict__ W,
                const float* __restrict__ bias,
                float* __restrict__ out) {
    extern __shared__ char dyn[];
    const int t = threadIdx.x;

    if (blockIdx.x < NGEMM) {
        // ===================== GEMM role =====================
        __half* sA = (__half*)dyn;                 // [CP_][LDA]
        __half* sB = (__half*)(dyn + SA_BYTES);    // [CP_][LDB]
        float*  sc = (float*)dyn;                  // [NT_][LDS_] (union)

        const int b  = blockIdx.x >> 6;
        const int n0 = (blockIdx.x & 63) * NT_;

        // sA: x tile (c<64), bias channel (c=64 -> 1.0), zero pad
        for (int lin = t; lin < CP_ * NT_; lin += 256) {
            int c  = lin >> 6;
            int nl = lin & (NT_ - 1);
            float v;
            if (c < 64)       v = x[((b * C_ + c) * N_) + n0 + nl];
            else if (c == 64) v = 1.0f;
            else              v = 0.0f;
            sA[c * LDA + nl] = __float2half(v);
        }
        // sB: fused weight transform (c<64)
        for (int lin = t; lin < C_ * OUT_; lin += 256) {
            int c = lin & 63;
            int r = lin >> 6;
            float a  = W[r * 128 + c];
            float bb = W[r * 128 + 64 + c];
            sB[c * LDB + r]      = __float2half(a - bb);
            sB[c * LDB + r + 64] = __float2half(bb);
        }
        // sB rows 64..79: bias row + zeros
        for (int lin = t; lin < 16 * R_; lin += 256) {
            int c = 64 + (lin >> 7);
            int r = lin & 127;
            float v = (c == 64 && r < 64) ? bias[r] : 0.0f;
            sB[c * LDB + r] = __float2half(v);
        }
        __syncthreads();

        {   // 8 warps: ws = warp&3 -> 16-node group, wr = warp>>2 -> 64-r half
            const int wp = t >> 5;
            const int ws = wp & 3;
            const int wr = wp >> 2;

            wmma::fragment<wmma::accumulator, 16, 16, 16, float> fc[4];
            #pragma unroll
            for (int rt = 0; rt < 4; rt++) wmma::fill_fragment(fc[rt], 0.0f);

            #pragma unroll
            for (int k = 0; k < 5; k++) {
                wmma::fragment<wmma::matrix_a, 16, 16, 16, __half, wmma::col_major> fa;
                wmma::load_matrix_sync(fa, sA + (k * 16) * LDA + ws * 16, LDA);
                #pragma unroll
                for (int rt = 0; rt < 4; rt++) {
                    wmma::fragment<wmma::matrix_b, 16, 16, 16, __half, wmma::row_major> fb;
                    wmma::load_matrix_sync(fb, sB + (k * 16) * LDB + wr * 64 + rt * 16, LDB);
                    wmma::mma_sync(fc[rt], fa, fb, fc[rt]);
                }
            }
            __syncthreads();
            #pragma unroll
            for (int rt = 0; rt < 4; rt++)
                wmma::store_matrix_sync(sc + (ws * 16) * LDS_ + wr * 64 + rt * 16,
                                        fc[rt], LDS_, wmma::mem_row_major);
            __syncthreads();
        }

        // Epilogue: fp16 convert, node-major store (bias already folded in)
        __half* outb = g_uvh + (size_t)(b * N_ + n0) * R_;
        for (int idx = t; idx < NT_ * 64; idx += 256) {
            int nl = idx >> 6;
            int rp = idx & 63;
            float lo = sc[nl * LDS_ + 2 * rp];
            float hi = sc[nl * LDS_ + 2 * rp + 1];
            *(__half2*)(outb + nl * R_ + 2 * rp) = __floats2half2_rn(lo, hi);
        }

        // Publish: every writing thread fences, then one thread signals.
        __threadfence();
        __syncthreads();
        if (t == 0) atomicAdd(&g_cnt[b], 1u);

    } else {
        // ===================== GATHER role =====================
        int2  (*sIdx)[17] = (int2 (*)[17])dyn;     // [GT_][17]  4,352 B
        float (*sm)[33]   = (float (*)[33])(dyn + GT_ * 17 * sizeof(int2)); // 8,448 B

        const int gid = blockIdx.x - NGEMM;
        const int b   = gid >> 7;                  // 128 gather tiles per batch
        const int n0  = (gid & 127) * GT_;

        // Stage indices (independent of gemm — overlaps producer work)
        for (int lin = t; lin < GT_ * K_; lin += 256) {
            int node = lin >> 4;
            int kk   = lin & 15;
            int e0 = edge[((0 * B_ + b) * N_ + n0 + node) * K_ + kk] & (N_ - 1); // -> v
            int e1 = edge[((1 * B_ + b) * N_ + n0 + node) * K_ + kk] & (N_ - 1); // -> u
            sIdx[node][kk] = make_int2(e0, e1);
        }
        __syncthreads();

        // Wait for this batch's 64 gemm tiles.
        if (t == 0) {
            while (*((volatile unsigned*)&g_cnt[b]) < 64u) { __nanosleep(128); }
        }
        __syncthreads();

        // Gather/max: 8 lanes per node, lane covers 8 channels via LDG.128.
        const int w    = t >> 5;
        const int lane = t & 31;
        const int h    = lane >> 3;          // node slot 0..3
        const int sl   = lane & 7;           // channel group
        const int nl   = 4 * w + h;          // node local 0..31
        const int co   = 8 * sl;

        const __half* uvb = g_uvh + (size_t)b * N_ * R_;

        __half2 m0 = __float2half2_rn(0.0f);
        __half2 m1 = m0, m2 = m0, m3 = m0;

        #pragma unroll
        for (int kk = 0; kk < K_; kk++) {
            int2 p = sIdx[nl][kk];
            uint4 uu = *(const uint4*)(uvb + p.y * R_ + co);
            uint4 vv = *(const uint4*)(uvb + p.x * R_ + 64 + co);
            m0 = __hmax2(m0, __hadd2(*(__half2*)&uu.x, *(__half2*)&vv.x));
            m1 = __hmax2(m1, __hadd2(*(__half2*)&uu.y, *(__half2*)&vv.y));
            m2 = __hmax2(m2, __hadd2(*(__half2*)&uu.z, *(__half2*)&vv.z));
            m3 = __hmax2(m3, __hadd2(*(__half2*)&uu.w, *(__half2*)&vv.w));
        }

        float2 f;
        f = __half22float2(m0); sm[co + 0][nl] = f.x; sm[co + 1][nl] = f.y;
        f = __half22float2(m1); sm[co + 2][nl] = f.x; sm[co + 3][nl] = f.y;
        f = __half22float2(m2); sm[co + 4][nl] = f.x; sm[co + 5][nl] = f.y;
        f = __half22float2(m3); sm[co + 6][nl] = f.x; sm[co + 7][nl] = f.y;
        __syncthreads();

        #pragma unroll
        for (int it = 0; it < 8; it++) {
            int lin = t + it * 256;          // 2048 values: 64 o x 32 n
            int o   = lin >> 5;
            int nn  = lin & 31;
            out[((b * OUT_ + o) * N_) + n0 + nn] = sm[o][nn];
        }

        // Replay-safe reset: last gather block zeroes the counters.
        __syncthreads();
        if (t == 0) {
            unsigned v = atomicAdd(&g_done, 1u);
            if (v == NGATH - 1) {
                #pragma unroll
                for (int i = 0; i < B_; i++) g_cnt[i] = 0;
                __threadfence();
                g_done = 0;
            }
        }
    }
}

// ---------------------------------------------------------------------------
extern "C" void kernel_launch(void* const* d_in, const int* in_sizes, int n_in,
                              void* d_out, int out_size) {
    const float* x    = (const float*)d_in[0];
    const int*   edge = (const int*)d_in[1];
    const float* W    = (const float*)d_in[2];
    const float* bias = (const float*)d_in[3];
    float*       out  = (float*)d_out;

    fused_graphconv<<<GRID_, 256, SMEM_BYTES>>>(x, edge, W, bias, out);
}

// round 14
// speedup vs baseline: 2.5813x; 1.0871x over previous
#include <cuda_runtime.h>
#include <cuda_fp16.h>
#include <mma.h>

using namespace nvcuda;

// Problem constants
#define B_    8
#define C_    64
#define CP_   80    // padded c: 64 real + 1 bias channel + 15 zero (5 k-tiles of 16)
#define N_    4096
#define K_    16
#define OUT_  64
#define R_    128   // 2*OUT rows: [0,64) = u (=(W1-W2)x + bias), [64,128) = v (=W2 x)

#define NT_   64             // nodes per block tile (gemm)
#define LDA   72             // sA: half[CP_][LDA]
#define LDB   136            // sB: half[CP_][LDB]
#define LDS_  136            // scratch: float[NT_][LDS_]
#define SA_BYTES (CP_ * LDA * 2)            // 11,520
#define SMEM_BYTES (NT_ * LDS_ * 4)         // 34,816 (scratch unions over sA+sB)

// Scratch (device global — no allocation allowed)
__device__ __half g_uvh[B_ * N_ * R_];   // [b][n][r] half: row = 256B = [u 0..63 | v 0..63]

// ---- PDL griddepcontrol (sm_90+) -------------------------------------------
__device__ __forceinline__ void gdc_wait() {
    asm volatile("griddepcontrol.wait;" ::: "memory");
}
__device__ __forceinline__ void gdc_launch_dependents() {
    asm volatile("griddepcontrol.launch_dependents;" ::: "memory");
}

// ---------------------------------------------------------------------------
// Kernel 1 (HMMA): uv[n][r] = sum_c x[c][n]*Wt[c][r], bias folded as c=64.
//   A = x^T (n x c) col_major -> smem [c][n] (x's natural layout)
//   B = Wt (c x r) row_major  -> smem [c][r] (transform's natural layout)
// Block 128 thr (4 warps), tile 64n x 128r; warp = 16n x 128r, 5 k-tiles.
// Triggers dependent launch at entry: all 512 blocks are wave-1 resident, so
// the gather grid starts (and stages indices) while this grid computes.
// ---------------------------------------------------------------------------
__global__ void __launch_bounds__(128) gemm_uv(const float* __restrict__ x,
                                               const float* __restrict__ W,
                                               const float* __restrict__ bias) {
    gdc_launch_dependents();

    extern __shared__ char dyn[];
    __half* sA = (__half*)dyn;                 // [CP_][LDA]
    __half* sB = (__half*)(dyn + SA_BYTES);    // [CP_][LDB]
    float*  sc = (float*)dyn;                  // [NT_][LDS_] (union, after sync)

    const int b  = blockIdx.y;
    const int n0 = blockIdx.x * NT_;
    const int t  = threadIdx.x;
    const int wn = t >> 5;        // warp id = n-subtile (16 nodes each)

    // ---- sA[c][nl]: x tile (c<64), bias channel (c=64 -> 1.0), zero pad
    for (int lin = t; lin < CP_ * NT_; lin += 128) {
        int c  = lin >> 6;
        int nl = lin & (NT_ - 1);
        float v;
        if (c < 64)       v = x[((b * C_ + c) * N_) + n0 + nl];
        else if (c == 64) v = 1.0f;
        else              v = 0.0f;
        sA[c * LDA + nl] = __float2half(v);
    }
    // ---- sB[c][r]: fused weight transform (c<64)
    for (int lin = t; lin < C_ * OUT_; lin += 128) {
        int c = lin & 63;
        int r = lin >> 6;                 // 0..63
        float a  = W[r * 128 + c];        // W1[r][c]
        float bb = W[r * 128 + 64 + c];   // W2[r][c]
        sB[c * LDB + r]      = __float2half(a - bb);
        sB[c * LDB + r + 64] = __float2half(bb);
    }
    // ---- sB rows 64..79: bias row + zeros
    for (int lin = t; lin < 16 * R_; lin += 128) {
        int c = 64 + (lin >> 7);
        int r = lin & 127;
        float v = (c == 64 && r < 64) ? bias[r] : 0.0f;
        sB[c * LDB + r] = __float2half(v);
    }
    __syncthreads();

    // ---- MMA: warp wn computes rows [wn*16, wn*16+16) x 128 r, 5 k-tiles
    wmma::fragment<wmma::matrix_a, 16, 16, 16, __half, wmma::col_major> fa[5];
    #pragma unroll
    for (int k = 0; k < 5; k++)
        wmma::load_matrix_sync(fa[k], sA + (k * 16) * LDA + wn * 16, LDA);

    wmma::fragment<wmma::accumulator, 16, 16, 16, float> fc[8];
    #pragma unroll
    for (int rt = 0; rt < 8; rt++) {
        wmma::fill_fragment(fc[rt], 0.0f);
        #pragma unroll
        for (int k = 0; k < 5; k++) {
            wmma::fragment<wmma::matrix_b, 16, 16, 16, __half, wmma::row_major> fb;
            wmma::load_matrix_sync(fb, sB + (k * 16) * LDB + rt * 16, LDB);
            wmma::mma_sync(fc[rt], fa[k], fb, fc[rt]);
        }
    }
    __syncthreads();   // all warps done with sA/sB before scratch overwrite

    #pragma unroll
    for (int rt = 0; rt < 8; rt++)
        wmma::store_matrix_sync(sc + (wn * 16) * LDS_ + rt * 16, fc[rt],
                                LDS_, wmma::mem_row_major);
    __syncthreads();

    // ---- epilogue: fp16 convert + node-major store (bias already folded in)
    __half* outb = g_uvh + (size_t)(b * N_ + n0) * R_;
    for (int idx = t; idx < NT_ * 64; idx += 128) {   // half2 granularity
        int nl = idx >> 6;
        int rp = idx & 63;
        float lo = sc[nl * LDS_ + 2 * rp];
        float hi = sc[nl * LDS_ + 2 * rp + 1];
        *(__half2*)(outb + nl * R_ + 2 * rp) = __floats2half2_rn(lo, hi);
    }
}

// ---------------------------------------------------------------------------
// Kernel 2: out[b][o][n] = max_k relu( u[b][i1(k)][o] + v[b][i0(k)][o] )
// Launched with programmaticStreamSerialization: starts under the gemm grid,
// stages its edge indices (independent), then gdc_wait for uvh visibility,
// then gathers at the L2 roofline (R10-measured: 12.9us @ 81.5% occ).
// ---------------------------------------------------------------------------
__global__ void __launch_bounds__(256) gather_max(const int* __restrict__ edge,
                                                  float* __restrict__ out) {
    __shared__ int2  sIdx[32][17];   // [node_local][k] (i0,i1); pad bank-clean
    __shared__ float sm[OUT_][33];   // transpose stage, pad 32->33

    const int b  = blockIdx.y;
    const int n0 = blockIdx.x * 32;
    const int t  = threadIdx.x;

    // Prologue (overlaps gemm): stage indices, both directions, coalesced.
    for (int lin = t; lin < 512; lin += 256) {
        int node = lin >> 4;
        int kk   = lin & 15;
        int e0 = edge[((0 * B_ + b) * N_ + n0 + node) * K_ + kk] & (N_ - 1); // neighbor -> v
        int e1 = edge[((1 * B_ + b) * N_ + n0 + node) * K_ + kk] & (N_ - 1); // center   -> u
        sIdx[node][kk] = make_int2(e0, e1);
    }
    __syncthreads();

    gdc_wait();   // primary grid (gemm) complete; uvh writes visible

    const int w    = t >> 5;
    const int lane = t & 31;
    const int h    = lane >> 3;          // node slot 0..3
    const int sl   = lane & 7;           // channel group: halves [8*sl, 8*sl+8)
    const int nl   = 4 * w + h;          // node local 0..31

    const __half* uvb = g_uvh + (size_t)b * N_ * R_;
    const int co = 8 * sl;               // half offset of this lane's channels

    __half2 m0 = __float2half2_rn(0.0f);
    __half2 m1 = m0, m2 = m0, m3 = m0;

    #pragma unroll
    for (int kk = 0; kk < K_; kk++) {
        int2 p = sIdx[nl][kk];           // broadcast within 8-lane group
        uint4 uu = *(const uint4*)(uvb + p.y * R_ + co);        // u[co..co+7]
        uint4 vv = *(const uint4*)(uvb + p.x * R_ + 64 + co);   // v[co..co+7]
        m0 = __hmax2(m0, __hadd2(*(__half2*)&uu.x, *(__half2*)&vv.x));
        m1 = __hmax2(m1, __hadd2(*(__half2*)&uu.y, *(__half2*)&vv.y));
        m2 = __hmax2(m2, __hadd2(*(__half2*)&uu.z, *(__half2*)&vv.z));
        m3 = __hmax2(m3, __hadd2(*(__half2*)&uu.w, *(__half2*)&vv.w));
    }

    // Transpose stage: lane owns channels co..co+7 of node nl.
    float2 f;
    f = __half22float2(m0); sm[co + 0][nl] = f.x; sm[co + 1][nl] = f.y;
    f = __half22float2(m1); sm[co + 2][nl] = f.x; sm[co + 3][nl] = f.y;
    f = __half22float2(m2); sm[co + 4][nl] = f.x; sm[co + 5][nl] = f.y;
    f = __half22float2(m3); sm[co + 6][nl] = f.x; sm[co + 7][nl] = f.y;
    __syncthreads();

    #pragma unroll
    for (int it = 0; it < 8; it++) {
        int lin = t + it * 256;          // 2048 values: 64 o x 32 n
        int o   = lin >> 5;
        int nn  = lin & 31;
        out[((b * OUT_ + o) * N_) + n0 + nn] = sm[o][nn];
    }
}

// ---------------------------------------------------------------------------
extern "C" void kernel_launch(void* const* d_in, const int* in_sizes, int n_in,
                              void* d_out, int out_size) {
    const float* x    = (const float*)d_in[0];
    const int*   edge = (const int*)d_in[1];
    const float* W    = (const float*)d_in[2];
    const float* bias = (const float*)d_in[3];
    float*       out  = (float*)d_out;

    // Primary: plain launch (trigger is in-kernel).
    {
        cudaLaunchConfig_t cfg = {};
        cfg.gridDim = dim3(N_ / NT_, B_, 1);
        cfg.blockDim = dim3(128, 1, 1);
        cfg.dynamicSmemBytes = SMEM_BYTES;       // 34,816 < 48KB default cap
        cudaLaunchKernelEx(&cfg, gemm_uv, x, W, bias);
    }

    // Secondary: programmatic early launch — overlaps with gemm.
    {
        cudaLaunchAttribute attr[1];
        attr[0].id = cudaLaunchAttributeProgrammaticStreamSerialization;
        attr[0].val.programmaticStreamSerializationAllowed = 1;

        cudaLaunchConfig_t cfg = {};
        cfg.attrs = attr;
        cfg.numAttrs = 1;
        cfg.gridDim = dim3(N_ / 32, B_, 1);
        cfg.blockDim = dim3(256, 1, 1);
        cfg.dynamicSmemBytes = 0;
        cudaLaunchKernelEx(&cfg, gather_max, edge, out);
    }
}

// round 15
// speedup vs baseline: 2.5880x; 1.0026x over previous
#include <cuda_runtime.h>
#include <cuda_fp16.h>
#include <mma.h>

using namespace nvcuda;

// Problem constants
#define B_    8
#define C_    64
#define CP_   80    // padded c: 64 real + 1 bias channel + 15 zero (5 k-tiles of 16)
#define N_    4096
#define K_    16
#define OUT_  64
#define R_    128   // 2*OUT rows: [0,64) = u (=(W1-W2)x + bias), [64,128) = v (=W2 x)

#define NT_   128            // nodes per gemm block tile
#define LDA   136            // sA: half[CP_][LDA]
#define LDB   136            // sB: half[CP_][LDB]
#define SA_BYTES (CP_ * LDA * 2)            // 21,760
#define SMEM_BYTES (SA_BYTES * 2)           // 43,520 (< 48KB default cap)

// Scratch (device global — no allocation allowed)
__device__ __half g_uvh[B_ * N_ * R_];   // [b][n][r] half: row = 256B = [u 0..63 | v 0..63]

// ---------------------------------------------------------------------------
// Kernel 1 (HMMA, fp16 accumulate): uv[n][r] = sum_c x[c][n]*Wt[c][r],
// bias folded as channel c=64. D written DIRECTLY to gmem by store_matrix_sync
// (no fp32 scratch, no epilogue, one __syncthreads total).
//   A = x^T (n x c) col_major -> smem [c][n] (x's natural layout)
//   B = Wt  (c x r) row_major -> smem [c][r] (transform's natural layout)
// Block 256 thr (8 warps), tile 128n x 128r; warp = 16n x 128r, 5 k-tiles.
// ---------------------------------------------------------------------------
__global__ void __launch_bounds__(256) gemm_uv(const float* __restrict__ x,
                                               const float* __restrict__ W,
                                               const float* __restrict__ bias) {
    extern __shared__ char dyn[];
    __half* sA = (__half*)dyn;                 // [CP_][LDA]
    __half* sB = (__half*)(dyn + SA_BYTES);    // [CP_][LDB]

    const int b  = blockIdx.y;
    const int n0 = blockIdx.x * NT_;
    const int t  = threadIdx.x;
    const int wp = t >> 5;        // warp id = 16-node subtile (8 of them)

    // ---- sA[c][nl]: x tile (c<64), bias channel (c=64 -> 1.0), zero pad
    for (int lin = t; lin < CP_ * NT_; lin += 256) {
        int c  = lin >> 7;
        int nl = lin & (NT_ - 1);
        float v;
        if (c < 64)       v = x[((b * C_ + c) * N_) + n0 + nl];
        else if (c == 64) v = 1.0f;
        else              v = 0.0f;
        sA[c * LDA + nl] = __float2half(v);
    }
    // ---- sB[c][r]: fused weight transform (c<64)
    for (int lin = t; lin < C_ * OUT_; lin += 256) {
        int c = lin & 63;
        int r = lin >> 6;                 // 0..63
        float a  = W[r * 128 + c];        // W1[r][c]
        float bb = W[r * 128 + 64 + c];   // W2[r][c]
        sB[c * LDB + r]      = __float2half(a - bb);
        sB[c * LDB + r + 64] = __float2half(bb);
    }
    // ---- sB rows 64..79: bias row + zeros
    for (int lin = t; lin < 16 * R_; lin += 256) {
        int c = 64 + (lin >> 7);
        int r = lin & 127;
        float v = (c == 64 && r < 64) ? bias[r] : 0.0f;
        sB[c * LDB + r] = __float2half(v);
    }
    __syncthreads();

    // ---- MMA: warp wp computes nodes [wp*16, wp*16+16) x 128 r, 5 k-tiles
    wmma::fragment<wmma::matrix_a, 16, 16, 16, __half, wmma::col_major> fa[5];
    #pragma unroll
    for (int k = 0; k < 5; k++)
        wmma::load_matrix_sync(fa[k], sA + (k * 16) * LDA + wp * 16, LDA);

    __half* outb = g_uvh + (size_t)(b * N_ + n0 + wp * 16) * R_;

    #pragma unroll
    for (int rt = 0; rt < 8; rt++) {
        wmma::fragment<wmma::accumulator, 16, 16, 16, __half> fc;
        wmma::fill_fragment(fc, __float2half(0.0f));
        #pragma unroll
        for (int k = 0; k < 5; k++) {
            wmma::fragment<wmma::matrix_b, 16, 16, 16, __half, wmma::row_major> fb;
            wmma::load_matrix_sync(fb, sB + (k * 16) * LDB + rt * 16, LDB);
            wmma::mma_sync(fc, fa[k], fb, fc);
        }
        // Direct global store: rows = nodes, cols = r, ld = 128 (node-major).
        wmma::store_matrix_sync(outb + rt * 16, fc, R_, wmma::mem_row_major);
    }
}

// ---------------------------------------------------------------------------
// Kernel 2 (R10-proven, at the L2-bytes roofline ~12.9us):
// out[b][o][n] = max_k relu( u[b][i1(k)][o] + v[b][i0(k)][o] )
// 4 nodes per warp, 8 lanes/node, LDG.128 gathers, half2 add/max.
// ---------------------------------------------------------------------------
__global__ void __launch_bounds__(256) gather_max(const int* __restrict__ edge,
                                                  float* __restrict__ out) {
    __shared__ int2  sIdx[32][17];   // [node_local][k] (i0,i1); pad bank-clean
    __shared__ float sm[OUT_][33];   // transpose stage, pad 32->33

    const int b  = blockIdx.y;
    const int n0 = blockIdx.x * 32;
    const int t  = threadIdx.x;

    // Stage indices: 512 (node,k) pairs, both directions, coalesced reads.
    for (int lin = t; lin < 512; lin += 256) {
        int node = lin >> 4;
        int kk   = lin & 15;
        int e0 = edge[((0 * B_ + b) * N_ + n0 + node) * K_ + kk] & (N_ - 1); // neighbor -> v
        int e1 = edge[((1 * B_ + b) * N_ + n0 + node) * K_ + kk] & (N_ - 1); // center   -> u
        sIdx[node][kk] = make_int2(e0, e1);
    }
    __syncthreads();

    const int w    = t >> 5;
    const int lane = t & 31;
    const int h    = lane >> 3;          // node slot 0..3
    const int sl   = lane & 7;           // channel group: halves [8*sl, 8*sl+8)
    const int nl   = 4 * w + h;          // node local 0..31

    const __half* uvb = g_uvh + (size_t)b * N_ * R_;
    const int co = 8 * sl;

    __half2 m0 = __float2half2_rn(0.0f);
    __half2 m1 = m0, m2 = m0, m3 = m0;

    #pragma unroll
    for (int kk = 0; kk < K_; kk++) {
        int2 p = sIdx[nl][kk];           // broadcast within 8-lane group
        uint4 uu = *(const uint4*)(uvb + p.y * R_ + co);        // u[co..co+7]
        uint4 vv = *(const uint4*)(uvb + p.x * R_ + 64 + co);   // v[co..co+7]
        m0 = __hmax2(m0, __hadd2(*(__half2*)&uu.x, *(__half2*)&vv.x));
        m1 = __hmax2(m1, __hadd2(*(__half2*)&uu.y, *(__half2*)&vv.y));
        m2 = __hmax2(m2, __hadd2(*(__half2*)&uu.z, *(__half2*)&vv.z));
        m3 = __hmax2(m3, __hadd2(*(__half2*)&uu.w, *(__half2*)&vv.w));
    }

    // Transpose stage: lane owns channels co..co+7 of node nl.
    float2 f;
    f = __half22float2(m0); sm[co + 0][nl] = f.x; sm[co + 1][nl] = f.y;
    f = __half22float2(m1); sm[co + 2][nl] = f.x; sm[co + 3][nl] = f.y;
    f = __half22float2(m2); sm[co + 4][nl] = f.x; sm[co + 5][nl] = f.y;
    f = __half22float2(m3); sm[co + 6][nl] = f.x; sm[co + 7][nl] = f.y;
    __syncthreads();

    #pragma unroll
    for (int it = 0; it < 8; it++) {
        int lin = t + it * 256;          // 2048 values: 64 o x 32 n
        int o   = lin >> 5;
        int nn  = lin & 31;
        out[((b * OUT_ + o) * N_) + n0 + nn] = sm[o][nn];
    }
}

// ---------------------------------------------------------------------------
extern "C" void kernel_launch(void* const* d_in, const int* in_sizes, int n_in,
                              void* d_out, int out_size) {
    const float* x    = (const float*)d_in[0];
    const int*   edge = (const int*)d_in[1];
    const float* W    = (const float*)d_in[2];
    const float* bias = (const float*)d_in[3];
    float*       out  = (float*)d_out;

    dim3 g1(N_ / NT_, B_);
    gemm_uv<<<g1, 256, SMEM_BYTES>>>(x, W, bias);

    dim3 g2(N_ / 32, B_);
    gather_max<<<g2, 256>>>(edge, out);
}

// round 16
// speedup vs baseline: 2.8398x; 1.0973x over previous
#include <cuda_runtime.h>
#include <cuda_fp16.h>
#include <mma.h>

using namespace nvcuda;

// Problem constants
#define B_    8
#define C_    64
#define CP_   80    // padded c: 64 real + 1 bias channel + 15 zero (5 k-tiles of 16)
#define N_    4096
#define K_    16
#define OUT_  64
#define R_    128   // 2*OUT rows: [0,64) = u (=(W1-W2)x + bias), [64,128) = v (=W2 x)

#define NT_   128            // nodes per gemm block tile
#define LDA   136            // sA: half[CP_][LDA]
#define LDB   136            // sB: half[CP_][LDB]
#define LDSC  136            // scratch: half[NT_][LDSC]
#define SA_BYTES (CP_ * LDA * 2)            // 21,760
#define SB_BYTES (CP_ * LDB * 2)            // 21,760
#define SC_BYTES (NT_ * LDSC * 2)           // 34,816
#define SMEM_BYTES (SA_BYTES + SB_BYTES)    // 43,520 (scratch unions inside)

// Scratch (device global — no allocation allowed)
__device__ __half g_uvh[B_ * N_ * R_];   // [b][n][r] half: row = 256B = [u 0..63 | v 0..63]

// ---------------------------------------------------------------------------
// Kernel 1 (HMMA, fp16 accumulate): uv[n][r] = sum_c x[c][n]*Wt[c][r],
// bias folded as channel c=64. Fragment stores bounce through a HALF smem
// scratch (coalescing), then a pure uint4 copy epilogue (no converts).
//   A = x^T (n x c) col_major -> smem [c][n] (x's natural layout)
//   B = Wt  (c x r) row_major -> smem [c][r] (transform's natural layout)
// Block 256 thr (8 warps), tile 128n x 128r; warp = 16n x 128r, 5 k-tiles.
// ---------------------------------------------------------------------------
__global__ void __launch_bounds__(256) gemm_uv(const float* __restrict__ x,
                                               const float* __restrict__ W,
                                               const float* __restrict__ bias) {
    extern __shared__ char dyn[];
    __half* sA = (__half*)dyn;                 // [CP_][LDA]
    __half* sB = (__half*)(dyn + SA_BYTES);    // [CP_][LDB]
    __half* sc = (__half*)dyn;                 // [NT_][LDSC] (union, after sync)

    const int b  = blockIdx.y;
    const int n0 = blockIdx.x * NT_;
    const int t  = threadIdx.x;
    const int wp = t >> 5;        // warp id = 16-node subtile (8 of them)

    // ---- sA[c][nl]: x tile (c<64), bias channel (c=64 -> 1.0), zero pad
    for (int lin = t; lin < CP_ * NT_; lin += 256) {
        int c  = lin >> 7;
        int nl = lin & (NT_ - 1);
        float v;
        if (c < 64)       v = x[((b * C_ + c) * N_) + n0 + nl];
        else if (c == 64) v = 1.0f;
        else              v = 0.0f;
        sA[c * LDA + nl] = __float2half(v);
    }
    // ---- sB[c][r]: fused weight transform (c<64)
    for (int lin = t; lin < C_ * OUT_; lin += 256) {
        int c = lin & 63;
        int r = lin >> 6;                 // 0..63
        float a  = W[r * 128 + c];        // W1[r][c]
        float bb = W[r * 128 + 64 + c];   // W2[r][c]
        sB[c * LDB + r]      = __float2half(a - bb);
        sB[c * LDB + r + 64] = __float2half(bb);
    }
    // ---- sB rows 64..79: bias row + zeros
    for (int lin = t; lin < 16 * R_; lin += 256) {
        int c = 64 + (lin >> 7);
        int r = lin & 127;
        float v = (c == 64 && r < 64) ? bias[r] : 0.0f;
        sB[c * LDB + r] = __float2half(v);
    }
    __syncthreads();

    // ---- MMA: warp wp computes nodes [wp*16, wp*16+16) x 128 r, 5 k-tiles
    wmma::fragment<wmma::matrix_a, 16, 16, 16, __half, wmma::col_major> fa[5];
    #pragma unroll
    for (int k = 0; k < 5; k++)
        wmma::load_matrix_sync(fa[k], sA + (k * 16) * LDA + wp * 16, LDA);

    wmma::fragment<wmma::accumulator, 16, 16, 16, __half> fc[8];
    #pragma unroll
    for (int rt = 0; rt < 8; rt++) {
        wmma::fill_fragment(fc[rt], __float2half(0.0f));
        #pragma unroll
        for (int k = 0; k < 5; k++) {
            wmma::fragment<wmma::matrix_b, 16, 16, 16, __half, wmma::row_major> fb;
            wmma::load_matrix_sync(fb, sB + (k * 16) * LDB + rt * 16, LDB);
            wmma::mma_sync(fc[rt], fa[k], fb, fc[rt]);
        }
    }
    __syncthreads();   // all warps done reading sA/sB before scratch overwrite

    #pragma unroll
    for (int rt = 0; rt < 8; rt++)
        wmma::store_matrix_sync(sc + (wp * 16) * LDSC + rt * 16, fc[rt],
                                LDSC, wmma::mem_row_major);
    __syncthreads();

    // ---- epilogue: pure uint4 copy, 256B contiguous per node in gmem
    __half* outb = g_uvh + (size_t)(b * N_ + n0) * R_;
    for (int idx = t; idx < NT_ * 16; idx += 256) {   // 16 uint4 per node row
        int nl = idx >> 4;
        int q  = idx & 15;
        uint4 v = *(const uint4*)(sc + nl * LDSC + q * 8);
        *(uint4*)(outb + nl * R_ + q * 8) = v;
    }
}

// ---------------------------------------------------------------------------
// Kernel 2 (R10-proven, at the L2-bytes roofline ~13us):
// out[b][o][n] = max_k relu( u[b][i1(k)][o] + v[b][i0(k)][o] )
// 4 nodes per warp, 8 lanes/node, LDG.128 gathers, half2 add/max.
// ---------------------------------------------------------------------------
__global__ void __launch_bounds__(256) gather_max(const int* __restrict__ edge,
                                                  float* __restrict__ out) {
    __shared__ int2  sIdx[32][17];   // [node_local][k] (i0,i1); pad bank-clean
    __shared__ float sm[OUT_][33];   // transpose stage, pad 32->33

    const int b  = blockIdx.y;
    const int n0 = blockIdx.x * 32;
    const int t  = threadIdx.x;

    // Stage indices: 512 (node,k) pairs, both directions, coalesced reads.
    for (int lin = t; lin < 512; lin += 256) {
        int node = lin >> 4;
        int kk   = lin & 15;
        int e0 = edge[((0 * B_ + b) * N_ + n0 + node) * K_ + kk] & (N_ - 1); // neighbor -> v
        int e1 = edge[((1 * B_ + b) * N_ + n0 + node) * K_ + kk] & (N_ - 1); // center   -> u
        sIdx[node][kk] = make_int2(e0, e1);
    }
    __syncthreads();

    const int w    = t >> 5;
    const int lane = t & 31;
    const int h    = lane >> 3;          // node slot 0..3
    const int sl   = lane & 7;           // channel group: halves [8*sl, 8*sl+8)
    const int nl   = 4 * w + h;          // node local 0..31

    const __half* uvb = g_uvh + (size_t)b * N_ * R_;
    const int co = 8 * sl;

    __half2 m0 = __float2half2_rn(0.0f);
    __half2 m1 = m0, m2 = m0, m3 = m0;

    #pragma unroll
    for (int kk = 0; kk < K_; kk++) {
        int2 p = sIdx[nl][kk];           // broadcast within 8-lane group
        uint4 uu = *(const uint4*)(uvb + p.y * R_ + co);        // u[co..co+7]
        uint4 vv = *(const uint4*)(uvb + p.x * R_ + 64 + co);   // v[co..co+7]
        m0 = __hmax2(m0, __hadd2(*(__half2*)&uu.x, *(__half2*)&vv.x));
        m1 = __hmax2(m1, __hadd2(*(__half2*)&uu.y, *(__half2*)&vv.y));
        m2 = __hmax2(m2, __hadd2(*(__half2*)&uu.z, *(__half2*)&vv.z));
        m3 = __hmax2(m3, __hadd2(*(__half2*)&uu.w, *(__half2*)&vv.w));
    }

    // Transpose stage: lane owns channels co..co+7 of node nl.
    float2 f;
    f = __half22float2(m0); sm[co + 0][nl] = f.x; sm[co + 1][nl] = f.y;
    f = __half22float2(m1); sm[co + 2][nl] = f.x; sm[co + 3][nl] = f.y;
    f = __half22float2(m2); sm[co + 4][nl] = f.x; sm[co + 5][nl] = f.y;
    f = __half22float2(m3); sm[co + 6][nl] = f.x; sm[co + 7][nl] = f.y;
    __syncthreads();

    #pragma unroll
    for (int it = 0; it < 8; it++) {
        int lin = t + it * 256;          // 2048 values: 64 o x 32 n
        int o   = lin >> 5;
        int nn  = lin & 31;
        out[((b * OUT_ + o) * N_) + n0 + nn] = sm[o][nn];
    }
}

// ---------------------------------------------------------------------------
extern "C" void kernel_launch(void* const* d_in, const int* in_sizes, int n_in,
                              void* d_out, int out_size) {
    const float* x    = (const float*)d_in[0];
    const int*   edge = (const int*)d_in[1];
    const float* W    = (const float*)d_in[2];
    const float* bias = (const float*)d_in[3];
    float*       out  = (float*)d_out;

    dim3 g1(N_ / NT_, B_);
    gemm_uv<<<g1, 256, SMEM_BYTES>>>(x, W, bias);

    dim3 g2(N_ / 32, B_);
    gather_max<<<g2, 256>>>(edge, out);
}